// round 8
// baseline (speedup 1.0000x reference)
#include <cuda_runtime.h>
#include <cuda_bf16.h>
#include <math.h>
#include <stdint.h>

#define NROWS     32768
#define CDIM      256
#define KCODES    1024
#define BLK_M     128
#define SPB       4096
#define ZQ_ELEMS  8388608

// ---- smem byte offsets (main kernel) ----
#define SO_B2S    0        // 1024 f -> 4096
#define SO_CV     4096     // 2*128*3 f -> 7168
#define SO_CK     7168     // 2*128*3 i -> 10240
#define SO_DRES   10240    // 128*6 f -> 13312
#define SO_SIDX   13312    // 128 i -> 13824
#define SO_RED    13824    // 8 f
#define SO_A      14336    // 2 splits x 128 x 528B = 135168 -> 149504
#define SO_B      149504   // 2 bufs x 33792 = 67584 -> 217088
#define SMEM_MAIN 217088
// phase-2 overlays
#define SO_ZS     14336    // 256*129 f = 132096 -> 146432 (inside A region)
#define SO_EBUF   149504   // 32*132 f = 16896
#define EPAD      132

#define ASTRIDE   528      // bytes per 256-bf16 row (+8 pad)
#define ASPLIT    67584    // 128*528
#define BSPLIT    16896    // 32*528
#define BBUF      33792    // 2 splits

__device__ __nv_bfloat16 gZ0[(size_t)NROWS * CDIM];
__device__ __nv_bfloat16 gZ1[(size_t)NROWS * CDIM];
__device__ __nv_bfloat16 gE0[(size_t)KCODES * CDIM];
__device__ __nv_bfloat16 gE1[(size_t)KCODES * CDIM];
__device__ float gA[NROWS];
__device__ float g_b2[KCODES];
__device__ int   g_counts[KCODES];
__device__ float g_sse;

__device__ __forceinline__ void mma16816(float* c, const uint32_t* a, const uint32_t* b) {
    asm volatile(
        "mma.sync.aligned.m16n8k16.row.col.f32.bf16.bf16.f32 "
        "{%0,%1,%2,%3}, {%4,%5,%6,%7}, {%8,%9}, {%0,%1,%2,%3};"
        : "+f"(c[0]), "+f"(c[1]), "+f"(c[2]), "+f"(c[3])
        : "r"(a[0]), "r"(a[1]), "r"(a[2]), "r"(a[3]), "r"(b[0]), "r"(b[1]));
}
__device__ __forceinline__ uint32_t ldfrag(const char* base, int r, int kbyte) {
    return *(const uint32_t*)(base + r * ASTRIDE + kbyte);
}
__device__ __forceinline__ bool better(float v1, int k1, float v2, int k2) {
    return v1 < v2 || (v1 == v2 && k1 < k2);
}

// ---------------------------------------------------------------------------
// prep_e: bf16x2 split of E + strict b2 + zero accumulators
// ---------------------------------------------------------------------------
__global__ void prep_e_kernel(const float* __restrict__ emb) {
    __shared__ float sb[32 * 257];
    const int tid = threadIdx.x;
    const int k0 = blockIdx.x * 32;
    const float4* src = (const float4*)(emb + (size_t)k0 * CDIM);
    for (int i = tid; i < 2048; i += 256) {
        float4 v = src[i];
        int r = i >> 6, c = (i & 63) * 4;
        float* d = &sb[r * 257 + c];
        d[0]=v.x; d[1]=v.y; d[2]=v.z; d[3]=v.w;
    }
    __syncthreads();
    if (tid < 32) {
        const float* e = &sb[tid * 257];
        float s = 0.f;
        for (int c = 0; c < CDIM; c++) s = __fadd_rn(s, __fmul_rn(e[c], e[c]));
        g_b2[k0 + tid] = s;
        g_counts[k0 + tid] = 0;
    }
    for (int i = tid; i < 32 * CDIM; i += 256) {
        int row = i >> 8, c = i & 255;
        float v = sb[row * 257 + c];
        __nv_bfloat16 h0 = __float2bfloat16(v);
        float r1 = v - __bfloat162float(h0);
        size_t gi = (size_t)(k0 + row) * CDIM + c;
        gE0[gi] = h0; gE1[gi] = __float2bfloat16(r1);
    }
    if (blockIdx.x == 0 && tid == 32) g_sse = 0.f;
}

// ---------------------------------------------------------------------------
// prep_z: transpose z -> [n][c], strict row sums, bf16x2 split
// ---------------------------------------------------------------------------
__global__ __launch_bounds__(256, 1)
void prep_z_kernel(const float* __restrict__ z) {
    extern __shared__ float Zs[];           // [256][129]
    const int tid = threadIdx.x, lane = tid & 31, w = tid >> 5;
    const int n0 = blockIdx.x * BLK_M;
    const int b = n0 >> 12, s0 = n0 & (SPB - 1);
    const float* zb = z + (size_t)b * (CDIM * SPB) + s0;
    const int lane4 = lane * 4;
    for (int c = w; c < CDIM; c += 8) {
        float4 v = *(const float4*)(zb + (size_t)c * SPB + lane4);
        float* d = &Zs[c * 129 + lane4];
        d[0]=v.x; d[1]=v.y; d[2]=v.z; d[3]=v.w;
    }
    __syncthreads();
    if (tid < BLK_M) {
        float s = 0.f;
        for (int c = 0; c < CDIM; c++) {
            float v = Zs[c * 129 + tid];
            s = __fadd_rn(s, __fmul_rn(v, v));
        }
        gA[n0 + tid] = s;
    }
    union { __nv_bfloat16 h[8]; uint4 v4; } u0, u1;
    for (int r = 0; r < 16; r++) {
        int m = w * 16 + r;
#pragma unroll
        for (int j = 0; j < 8; j++) {
            float v = Zs[(lane * 8 + j) * 129 + m];
            __nv_bfloat16 h0 = __float2bfloat16(v);
            u0.h[j] = h0; u1.h[j] = __float2bfloat16(v - __bfloat162float(h0));
        }
        size_t ro = (size_t)(n0 + m) * CDIM + lane * 8;
        *(uint4*)(gZ0 + ro) = u0.v4;
        *(uint4*)(gZ1 + ro) = u1.v4;
    }
}

// ---------------------------------------------------------------------------
// main: bf16-split HMMA distance GEMM + per-half top-3 + exact recheck + epilogue
// ---------------------------------------------------------------------------
__global__ __launch_bounds__(256, 1)
void vq_main_kernel(const float* __restrict__ z, const float* __restrict__ emb,
                    float* __restrict__ out, int writeIdx) {
    extern __shared__ char sm[];
    float* b2s  = (float*)(sm + SO_B2S);
    float* cv   = (float*)(sm + SO_CV);
    int*   ck   = (int*)(sm + SO_CK);
    float* dres = (float*)(sm + SO_DRES);
    int*   sIdx = (int*)(sm + SO_SIDX);
    float* red  = (float*)(sm + SO_RED);

    const int tid = threadIdx.x, wid = tid >> 5, lane = tid & 31;
    const int wm = wid & 3, wn = wid >> 2;        // 4 M-warps x 2 N-warps
    const int gq = lane >> 2, tq = lane & 3;      // quad row / quad col
    const int n0 = blockIdx.x * BLK_M;
    const int b = n0 >> 12, s0 = n0 & (SPB - 1);

    for (int i = tid; i < KCODES; i += 256) b2s[i] = g_b2[i];

    // ---- stage A (both splits), row-major bf16 stride 528B ----
    {
        const __nv_bfloat16* za[2] = { gZ0 + (size_t)n0 * CDIM, gZ1 + (size_t)n0 * CDIM };
        for (int i = tid; i < 8192; i += 256) {      // 2*128*32 uint4
            int split = i >> 12, r = (i >> 5) & 127, c8 = i & 31;
            uint4 v = *(const uint4*)(za[split] + (size_t)r * CDIM + c8 * 8);
            *(uint4*)(sm + SO_A + split * ASPLIT + r * ASTRIDE + c8 * 16) = v;
        }
    }
    // ---- stage B chunk 0 ----
    {
        for (int j = 0; j < 8; j++) {
            int idx = tid + 256 * j;
            int split = idx >> 10, r = (idx >> 5) & 31, c8 = idx & 31;
            const __nv_bfloat16* ge = split ? gE1 : gE0;
            uint4 v = *(const uint4*)(ge + (size_t)r * CDIM + c8 * 8);
            *(uint4*)(sm + SO_B + split * BSPLIT + r * ASTRIDE + c8 * 16) = v;
        }
    }
    __syncthreads();

    // per-slot top-3 (4 row-slots per thread)
    float tv[4][3]; int tk[4][3];
#pragma unroll
    for (int s = 0; s < 4; s++) { tv[s][0]=tv[s][1]=tv[s][2]=3.4e38f; tk[s][0]=tk[s][1]=tk[s][2]=KCODES; }

    const char* A0 = sm + SO_A;
    const char* A1 = A0 + ASPLIT;

    for (int c = 0; c < 32; c++) {
        // prefetch next B chunk into regs
        uint4 pre[8];
        const int hasNext = (c + 1 < 32);
        if (hasNext) {
#pragma unroll
            for (int j = 0; j < 8; j++) {
                int idx = tid + 256 * j;
                int split = idx >> 10, r = (idx >> 5) & 31, c8 = idx & 31;
                const __nv_bfloat16* ge = split ? gE1 : gE0;
                pre[j] = *(const uint4*)(ge + ((size_t)(c + 1) * 32 + r) * CDIM + c8 * 8);
            }
        }
        const char* Bb = sm + SO_B + (c & 1) * BBUF;
        const char* B0 = Bb, *B1 = Bb + BSPLIT;

        float acc[2][2][4];
#pragma unroll
        for (int mi = 0; mi < 2; mi++)
#pragma unroll
            for (int ni = 0; ni < 2; ni++)
#pragma unroll
                for (int j = 0; j < 4; j++) acc[mi][ni][j] = 0.f;

        // pass group 1: A0 x (B0, B1)
#pragma unroll 4
        for (int ks = 0; ks < 16; ks++) {
            int kb = ks * 32 + tq * 4;              // byte offset of k pair
            uint32_t a[2][4];
#pragma unroll
            for (int mi = 0; mi < 2; mi++) {
                int rb = wm * 32 + mi * 16 + gq;
                a[mi][0] = ldfrag(A0, rb,     kb);
                a[mi][1] = ldfrag(A0, rb + 8, kb);
                a[mi][2] = ldfrag(A0, rb,     kb + 16);
                a[mi][3] = ldfrag(A0, rb + 8, kb + 16);
            }
#pragma unroll
            for (int sp = 0; sp < 2; sp++) {
                const char* Bx = sp ? B1 : B0;
                uint32_t bf[2][2];
#pragma unroll
                for (int ni = 0; ni < 2; ni++) {
                    int nb = wn * 16 + ni * 8 + gq;
                    bf[ni][0] = ldfrag(Bx, nb, kb);
                    bf[ni][1] = ldfrag(Bx, nb, kb + 16);
                }
#pragma unroll
                for (int mi = 0; mi < 2; mi++)
#pragma unroll
                    for (int ni = 0; ni < 2; ni++)
                        mma16816(acc[mi][ni], a[mi], bf[ni]);
            }
        }
        // pass 3: A1 x B0
#pragma unroll 4
        for (int ks = 0; ks < 16; ks++) {
            int kb = ks * 32 + tq * 4;
            uint32_t a[2][4];
#pragma unroll
            for (int mi = 0; mi < 2; mi++) {
                int rb = wm * 32 + mi * 16 + gq;
                a[mi][0] = ldfrag(A1, rb,     kb);
                a[mi][1] = ldfrag(A1, rb + 8, kb);
                a[mi][2] = ldfrag(A1, rb,     kb + 16);
                a[mi][3] = ldfrag(A1, rb + 8, kb + 16);
            }
            uint32_t bf[2][2];
#pragma unroll
            for (int ni = 0; ni < 2; ni++) {
                int nb = wn * 16 + ni * 8 + gq;
                bf[ni][0] = ldfrag(B0, nb, kb);
                bf[ni][1] = ldfrag(B0, nb, kb + 16);
            }
#pragma unroll
            for (int mi = 0; mi < 2; mi++)
#pragma unroll
                for (int ni = 0; ni < 2; ni++)
                    mma16816(acc[mi][ni], a[mi], bf[ni]);
        }

        // fold into per-slot top-3 (score = b2 - 2*dot)
#pragma unroll
        for (int mi = 0; mi < 2; mi++)
#pragma unroll
            for (int ni = 0; ni < 2; ni++)
#pragma unroll
                for (int j = 0; j < 4; j++) {
                    int code = c * 32 + wn * 16 + ni * 8 + tq * 2 + (j & 1);
                    int s = mi * 2 + (j >> 1);
                    float t = fmaf(-2.f, acc[mi][ni][j], b2s[code]);
                    if (t < tv[s][0]) {
                        tv[s][2]=tv[s][1]; tk[s][2]=tk[s][1];
                        tv[s][1]=tv[s][0]; tk[s][1]=tk[s][0];
                        tv[s][0]=t; tk[s][0]=code;
                    } else if (t < tv[s][1]) {
                        tv[s][2]=tv[s][1]; tk[s][2]=tk[s][1];
                        tv[s][1]=t; tk[s][1]=code;
                    } else if (t < tv[s][2]) {
                        tv[s][2]=t; tk[s][2]=code;
                    }
                }

        if (hasNext) {
            char* Bn = sm + SO_B + ((c + 1) & 1) * BBUF;
#pragma unroll
            for (int j = 0; j < 8; j++) {
                int idx = tid + 256 * j;
                int split = idx >> 10, r = (idx >> 5) & 31, c8 = idx & 31;
                *(uint4*)(Bn + split * BSPLIT + r * ASTRIDE + c8 * 16) = pre[j];
            }
        }
        __syncthreads();
    }

    // ---- quad merge (top-3 of two sorted triples), offsets 1 and 2 ----
#pragma unroll
    for (int s = 0; s < 4; s++) {
#pragma unroll
        for (int off = 1; off <= 2; off <<= 1) {
            float b0 = __shfl_xor_sync(0xffffffffu, tv[s][0], off);
            float b1 = __shfl_xor_sync(0xffffffffu, tv[s][1], off);
            float b2v = __shfl_xor_sync(0xffffffffu, tv[s][2], off);
            int   c0 = __shfl_xor_sync(0xffffffffu, tk[s][0], off);
            int   c1 = __shfl_xor_sync(0xffffffffu, tk[s][1], off);
            int   c2 = __shfl_xor_sync(0xffffffffu, tk[s][2], off);
            float a0 = tv[s][0], a1 = tv[s][1], a2 = tv[s][2];
            int   x0 = tk[s][0], x1 = tk[s][1], x2 = tk[s][2];
            float o0, o1, o2; int p0, p1, p2;
            if (better(a0, x0, b0, c0)) {
                o0 = a0; p0 = x0;
                if (better(a1, x1, b0, c0)) {
                    o1 = a1; p1 = x1;
                    if (better(a2, x2, b0, c0)) { o2 = a2; p2 = x2; }
                    else                        { o2 = b0; p2 = c0; }
                } else {
                    o1 = b0; p1 = c0;
                    if (better(a1, x1, b1, c1)) { o2 = a1; p2 = x1; }
                    else                        { o2 = b1; p2 = c1; }
                }
            } else {
                o0 = b0; p0 = c0;
                if (better(a0, x0, b1, c1)) {
                    o1 = a0; p1 = x0;
                    if (better(a1, x1, b1, c1)) { o2 = a1; p2 = x1; }
                    else                        { o2 = b1; p2 = c1; }
                } else {
                    o1 = b1; p1 = c1;
                    if (better(a0, x0, b2v, c2)) { o2 = a0; p2 = x0; }
                    else                         { o2 = b2v; p2 = c2; }
                }
            }
            tv[s][0]=o0; tv[s][1]=o1; tv[s][2]=o2;
            tk[s][0]=p0; tk[s][1]=p1; tk[s][2]=p2;
        }
        if (tq == 0) {
            int row = wm * 32 + (s >> 1) * 16 + (s & 1) * 8 + gq;
            int base = (wn * 128 + row) * 3;
            cv[base]=tv[s][0]; cv[base+1]=tv[s][1]; cv[base+2]=tv[s][2];
            ck[base]=tk[s][0]; ck[base+1]=tk[s][1]; ck[base+2]=tk[s][2];
        }
    }
    __syncthreads();

    // ---- reload Zs fp32 (overlay on A region) ----
    float* Zs = (float*)(sm + SO_ZS);
    const float* zb = z + (size_t)b * (CDIM * SPB) + s0;
    {
        int lane4 = lane * 4;
        for (int cc = wid; cc < CDIM; cc += 8) {
            float4 v = *(const float4*)(zb + (size_t)cc * SPB + lane4);
            float* d = &Zs[cc * 129 + lane4];
            d[0]=v.x; d[1]=v.y; d[2]=v.z; d[3]=v.w;
        }
    }
    __syncthreads();

    // ---- exact recheck of 6 candidates per row (sequential fmaf chain, R3 assoc) ----
    for (int r3 = 0; r3 < 3; r3++) {
        int idx = tid + 256 * r3;          // 0..767
        int row = idx / 6, cnd = idx - row * 6;
        int half = cnd >= 3, slot = cnd - half * 3;
        int k = ck[(half * 128 + row) * 3 + slot];
        const float* e = emb + (size_t)k * CDIM;
        float p = 0.f;
        for (int cc = 0; cc < CDIM; cc++)
            p = fmaf(Zs[cc * 129 + row], e[cc], p);
        dres[idx] = __fsub_rn(__fadd_rn(gA[n0 + row], g_b2[k]), __fadd_rn(p, p));
    }
    __syncthreads();
    if (tid < BLK_M) {
        float bv = 3.4e38f; int bk = KCODES;
        for (int cnd = 0; cnd < 6; cnd++) {
            int half = cnd >= 3, slot = cnd - half * 3;
            int k = ck[(half * 128 + tid) * 3 + slot];
            float d = dres[tid * 6 + cnd];
            if (better(d, k, bv, bk)) { bv = d; bk = k; }
        }
        sIdx[tid] = bk;
        atomicAdd(&g_counts[bk], 1);
        if (writeIdx) out[(size_t)ZQ_ELEMS + 2 + n0 + tid] = (float)bk;
    }
    __syncthreads();

    // ---- z_q gather + straight-through + SSE ----
    float* Ebuf = (float*)(sm + SO_EBUF);
    float lsse = 0.f;
    float* zqout = out + (size_t)b * (CDIM * SPB) + s0;
    for (int p = 0; p < 8; p++) {
        __syncthreads();
#pragma unroll
        for (int r = 0; r < 16; r++) {
            int m = wid * 16 + r;
            Ebuf[lane * EPAD + m] = emb[(size_t)sIdx[m] * CDIM + p * 32 + lane];
        }
        __syncthreads();
#pragma unroll
        for (int j = 0; j < 16; j++) {
            int id = tid + 256 * j;
            int cc = id >> 7, m = id & 127;
            float v = Ebuf[cc * EPAD + m];
            int c = p * 32 + cc;
            float zv = Zs[c * 129 + m];
            float diff = __fsub_rn(v, zv);
            lsse = fmaf(diff, diff, lsse);
            zqout[(size_t)c * SPB + m] = __fadd_rn(zv, diff);
        }
    }
#pragma unroll
    for (int o = 16; o > 0; o >>= 1) lsse += __shfl_xor_sync(0xffffffffu, lsse, o);
    if (lane == 0) red[wid] = lsse;
    __syncthreads();
    if (tid == 0) {
        float s = 0.f;
        for (int i = 0; i < 8; i++) s += red[i];
        atomicAdd(&g_sse, s);
    }
}

// ---------------------------------------------------------------------------
__global__ void finalize_kernel(float* __restrict__ out) {
    __shared__ float red[32];
    int t = threadIdx.x;
    float c = (float)g_counts[t];
    float e = c * (1.0f / 32768.0f);
    float h = e * logf(e + 1e-10f);
#pragma unroll
    for (int o = 16; o > 0; o >>= 1) h += __shfl_xor_sync(0xffffffffu, h, o);
    if ((t & 31) == 0) red[t >> 5] = h;
    __syncthreads();
    if (t < 32) {
        float v = red[t];
#pragma unroll
        for (int o = 16; o > 0; o >>= 1) v += __shfl_xor_sync(0xffffffffu, v, o);
        if (t == 0) {
            out[ZQ_ELEMS]     = 1.25f * g_sse * (1.0f / 8388608.0f);
            out[ZQ_ELEMS + 1] = expf(-v);
        }
    }
}

// ---------------------------------------------------------------------------
extern "C" void kernel_launch(void* const* d_in, const int* in_sizes, int n_in,
                              void* d_out, int out_size) {
    const float* z   = (const float*)d_in[0];
    const float* emb = (const float*)d_in[1];
    if (n_in >= 2 && in_sizes[0] == KCODES * CDIM && in_sizes[1] == ZQ_ELEMS) {
        z = (const float*)d_in[1]; emb = (const float*)d_in[0];
    }
    float* out = (float*)d_out;
    int writeScalars = out_size >= ZQ_ELEMS + 2;
    int writeIdx     = out_size >= ZQ_ELEMS + 2 + NROWS;

    cudaFuncSetAttribute(prep_z_kernel, cudaFuncAttributeMaxDynamicSharedMemorySize, 132096);
    cudaFuncSetAttribute(vq_main_kernel, cudaFuncAttributeMaxDynamicSharedMemorySize, SMEM_MAIN);

    prep_e_kernel<<<32, 256>>>(emb);
    prep_z_kernel<<<NROWS / BLK_M, 256, 132096>>>(z);
    vq_main_kernel<<<NROWS / BLK_M, 256, SMEM_MAIN>>>(z, emb, out, writeIdx);
    if (writeScalars) finalize_kernel<<<1, 1024>>>(out);
}